// round 12
// baseline (speedup 1.0000x reference)
#include <cuda_runtime.h>

// DynamicNet_17695265259799 — exact closed form of the reference. FINAL.
//
// reference(): Wm = tril(W,-1) keeps W[i,j] only for i > j, but the scan
// fills nodes j = 1..n-1 in ASCENDING order, so at step j every potential
// source activation A[:,i], i > j is still exactly 0.0f. Hence
// s_j == b[j] exactly (0 * finite == 0 in IEEE fp32), the output node is
// linear, and the result is b[n-1] broadcast over the batch — independent
// of x and W for all finite inputs. rel_err is exactly 0.0 by construction.
//
// Converged (11 rounds). CTA-shape optimum bracketed both sides
// (ncu kernel us): 128x1024x2=5.28 | 256x512x2=4.29-4.51 (x3, THIS) |
// 512x512=4.58 | 256x256x4=4.61 | 1024x256=4.22-4.67 | 2048x128=6.08.
// Kernel = launch ramp + 4MiB L2 store drain (DRAM 0%, L2 ~8%); dur adds
// ~2.2us fixed graph-replay overhead. dur_us pinned at 6.6 +/- 0.3.

__global__ __launch_bounds__(512)
void dynamicnet_broadcast_exact(const float* __restrict__ bias_last,
                                float4* __restrict__ out4) {
    const float v = __ldg(bias_last);
    const int T = gridDim.x * blockDim.x;            // 131072
    const int tid = blockIdx.x * blockDim.x + threadIdx.x;
    const float4 v4 = make_float4(v, v, v, v);
    // Two independent, coalesced STG.128 (grid exactly covers 2*T = n4).
    out4[tid]     = v4;
    out4[tid + T] = v4;
}

// Guarded fallback for sizes not exactly covered (never taken here).
__global__ __launch_bounds__(256)
void dynamicnet_broadcast_guarded(const float* __restrict__ bias_last,
                                  float4* __restrict__ out4, int n4) {
    const float v = __ldg(bias_last);
    const int tid = blockIdx.x * blockDim.x + threadIdx.x;
    if (tid < n4) out4[tid] = make_float4(v, v, v, v);
}

__global__ void dynamicnet_tail_kernel(const float* __restrict__ bias_last,
                                       float* __restrict__ out,
                                       int start, int out_elems) {
    const float v = __ldg(bias_last);
    const int i = start + threadIdx.x;
    if (i < out_elems) out[i] = v;
}

extern "C" void kernel_launch(void* const* d_in, const int* in_sizes, int n_in,
                              void* d_out, int out_size) {
    // metadata order: x [BATCH,1] f32, W [n,n] f32, b [n] f32
    const float* bias = (const float*)d_in[2];
    const float* bias_last = bias + (in_sizes[2] - 1);  // &b[65]

    float* out = (float*)d_out;
    float4* out4 = reinterpret_cast<float4*>(out);
    const int n4 = out_size >> 2;  // 262144 float4 slots

    const int threads = 512;
    const int per_block = threads * 2;  // 2 float4 per thread
    if (n4 > 0 && (n4 % per_block) == 0) {
        // Exact cover: 256 blocks x 512 threads x 2 stores for 1M elems.
        dynamicnet_broadcast_exact<<<n4 / per_block, threads>>>(bias_last, out4);
    } else if (n4 > 0) {
        dynamicnet_broadcast_guarded<<<(n4 + 255) / 256, 256>>>(
            bias_last, out4, n4);
    }

    const int tail = out_size - (n4 << 2);
    if (tail > 0) {
        dynamicnet_tail_kernel<<<1, 32>>>(bias_last, out, n4 << 2, out_size);
    }
}

// round 13
// speedup vs baseline: 1.0048x; 1.0048x over previous
#include <cuda_runtime.h>

// DynamicNet_17695265259799 — exact closed form of the reference. FINAL.
//
// reference(): Wm = tril(W,-1) keeps W[i,j] only for i > j, but the scan
// fills nodes j = 1..n-1 in ASCENDING order, so at step j every potential
// source activation A[:,i], i > j is still exactly 0.0f. Hence
// s_j == b[j] exactly (0 * finite == 0 in IEEE fp32), the output node is
// linear, and the result is b[n-1] broadcast over the batch — independent
// of x and W for all finite inputs. rel_err is exactly 0.0 by construction.
//
// Converged (12 rounds, optimum reproduced x4). CTA-shape sweep
// (ncu kernel us): 128x1024x2=5.28 | 256x512x2=4.26-4.51 (THIS) |
// 512x512=4.58 | 256x256x4=4.61 | 1024x256=4.22-4.67 | 2048x128=6.08.
// Kernel = launch ramp + 4MiB L2 store drain (DRAM 0%, L2 ~9%); dur adds
// ~2.2us fixed graph-replay overhead. dur_us pinned at 6.6 +/- 0.3.

__global__ __launch_bounds__(512)
void dynamicnet_broadcast_exact(const float* __restrict__ bias_last,
                                float4* __restrict__ out4) {
    const float v = __ldg(bias_last);
    const int T = gridDim.x * blockDim.x;            // 131072
    const int tid = blockIdx.x * blockDim.x + threadIdx.x;
    const float4 v4 = make_float4(v, v, v, v);
    // Two independent, coalesced STG.128 (grid exactly covers 2*T = n4).
    out4[tid]     = v4;
    out4[tid + T] = v4;
}

// Guarded fallback for sizes not exactly covered (never taken here).
__global__ __launch_bounds__(256)
void dynamicnet_broadcast_guarded(const float* __restrict__ bias_last,
                                  float4* __restrict__ out4, int n4) {
    const float v = __ldg(bias_last);
    const int tid = blockIdx.x * blockDim.x + threadIdx.x;
    if (tid < n4) out4[tid] = make_float4(v, v, v, v);
}

__global__ void dynamicnet_tail_kernel(const float* __restrict__ bias_last,
                                       float* __restrict__ out,
                                       int start, int out_elems) {
    const float v = __ldg(bias_last);
    const int i = start + threadIdx.x;
    if (i < out_elems) out[i] = v;
}

extern "C" void kernel_launch(void* const* d_in, const int* in_sizes, int n_in,
                              void* d_out, int out_size) {
    // metadata order: x [BATCH,1] f32, W [n,n] f32, b [n] f32
    const float* bias = (const float*)d_in[2];
    const float* bias_last = bias + (in_sizes[2] - 1);  // &b[65]

    float* out = (float*)d_out;
    float4* out4 = reinterpret_cast<float4*>(out);
    const int n4 = out_size >> 2;  // 262144 float4 slots

    const int threads = 512;
    const int per_block = threads * 2;  // 2 float4 per thread
    if (n4 > 0 && (n4 % per_block) == 0) {
        // Exact cover: 256 blocks x 512 threads x 2 stores for 1M elems.
        dynamicnet_broadcast_exact<<<n4 / per_block, threads>>>(bias_last, out4);
    } else if (n4 > 0) {
        dynamicnet_broadcast_guarded<<<(n4 + 255) / 256, 256>>>(
            bias_last, out4, n4);
    }

    const int tail = out_size - (n4 << 2);
    if (tail > 0) {
        dynamicnet_tail_kernel<<<1, 32>>>(bias_last, out, n4 << 2, out_size);
    }
}

// round 14
// speedup vs baseline: 1.0297x; 1.0248x over previous
#include <cuda_runtime.h>

// DynamicNet_17695265259799 — exact closed form of the reference. FINAL.
//
// reference(): Wm = tril(W,-1) keeps W[i,j] only for i > j, but the scan
// fills nodes j = 1..n-1 in ASCENDING order, so at step j every potential
// source activation A[:,i], i > j is still exactly 0.0f. Hence
// s_j == b[j] exactly (0 * finite == 0 in IEEE fp32), the output node is
// linear, and the result is b[n-1] broadcast over the batch — independent
// of x and W for all finite inputs. rel_err is exactly 0.0 by construction.
//
// Converged (13 rounds, optimum reproduced x5). CTA-shape sweep
// (ncu kernel us): 128x1024x2=5.28 | 256x512x2=4.26-4.51 (THIS) |
// 512x512=4.58 | 256x256x4=4.61 | 1024x256=4.22-4.67 | 2048x128=6.08.
// Kernel = launch ramp (~5000cyc) + 4MiB L2 store drain (DRAM 0%, L2 ~9%);
// dur adds ~2.2us fixed graph-replay overhead. dur_us pinned at 6.6 +/- 0.3;
// occupancy/issue proven non-binding by intervention.

__global__ __launch_bounds__(512)
void dynamicnet_broadcast_exact(const float* __restrict__ bias_last,
                                float4* __restrict__ out4) {
    const float v = __ldg(bias_last);
    const int T = gridDim.x * blockDim.x;            // 131072
    const int tid = blockIdx.x * blockDim.x + threadIdx.x;
    const float4 v4 = make_float4(v, v, v, v);
    // Two independent, coalesced STG.128 (grid exactly covers 2*T = n4).
    out4[tid]     = v4;
    out4[tid + T] = v4;
}

// Guarded fallback for sizes not exactly covered (never taken here).
__global__ __launch_bounds__(256)
void dynamicnet_broadcast_guarded(const float* __restrict__ bias_last,
                                  float4* __restrict__ out4, int n4) {
    const float v = __ldg(bias_last);
    const int tid = blockIdx.x * blockDim.x + threadIdx.x;
    if (tid < n4) out4[tid] = make_float4(v, v, v, v);
}

__global__ void dynamicnet_tail_kernel(const float* __restrict__ bias_last,
                                       float* __restrict__ out,
                                       int start, int out_elems) {
    const float v = __ldg(bias_last);
    const int i = start + threadIdx.x;
    if (i < out_elems) out[i] = v;
}

extern "C" void kernel_launch(void* const* d_in, const int* in_sizes, int n_in,
                              void* d_out, int out_size) {
    // metadata order: x [BATCH,1] f32, W [n,n] f32, b [n] f32
    const float* bias = (const float*)d_in[2];
    const float* bias_last = bias + (in_sizes[2] - 1);  // &b[65]

    float* out = (float*)d_out;
    float4* out4 = reinterpret_cast<float4*>(out);
    const int n4 = out_size >> 2;  // 262144 float4 slots

    const int threads = 512;
    const int per_block = threads * 2;  // 2 float4 per thread
    if (n4 > 0 && (n4 % per_block) == 0) {
        // Exact cover: 256 blocks x 512 threads x 2 stores for 1M elems.
        dynamicnet_broadcast_exact<<<n4 / per_block, threads>>>(bias_last, out4);
    } else if (n4 > 0) {
        dynamicnet_broadcast_guarded<<<(n4 + 255) / 256, 256>>>(
            bias_last, out4, n4);
    }

    const int tail = out_size - (n4 << 2);
    if (tail > 0) {
        dynamicnet_tail_kernel<<<1, 32>>>(bias_last, out, n4 << 2, out_size);
    }
}